// round 1
// baseline (speedup 1.0000x reference)
#include <cuda_runtime.h>
#include <cuda_bf16.h>
#include <math.h>

// Problem constants
#define BATCH   4
#define SEQ     2048
#define DIM     1024
#define HEADS   8
#define HDIM    128            // DIM / HEADS
#define QKV_DIM (3 * DIM)      // 3072

// Scratch (module globals — allowed; no runtime allocation)
__device__ float g_qkv[(size_t)BATCH * SEQ * QKV_DIM];            // 100.7 MB
__device__ float g_scores[(size_t)BATCH * HEADS * SEQ * SEQ];     // 536.9 MB
__device__ float g_ctx[(size_t)BATCH * SEQ * DIM];                // 33.6 MB

// ---------------------------------------------------------------------------
// Generic batched SGEMM, NT form:  C[m,n] = alpha * sum_k A[m,k] * B[n,k] + bias[n]
// A row-major (lda), B row-major [N,K] (ldb), C row-major (ldc).
// Batch index z = blockIdx.z, decomposed as outer = z>>3, inner = z&7.
// Tile: 64x64x16, 256 threads, 4x4 per-thread micro-tile.
// ---------------------------------------------------------------------------
__global__ __launch_bounds__(256)
void gemm_nt(const float* __restrict__ A, int lda, long aOut, long aIn,
             const float* __restrict__ Bm, int ldb, long bOut, long bIn,
             const float* __restrict__ bias,
             float* __restrict__ C, int ldc, long cOut, long cIn,
             int K, float alpha)
{
    int z = blockIdx.z;
    int bo = z >> 3, bi = z & 7;
    A  += (size_t)bo * aOut + (size_t)bi * aIn;
    Bm += (size_t)bo * bOut + (size_t)bi * bIn;
    C  += (size_t)bo * cOut + (size_t)bi * cIn;

    __shared__ float As[16][65];
    __shared__ float Bs[16][65];

    const int t  = threadIdx.x;
    const int tx = t & 15;        // -> n = bn + tx + 16*j
    const int ty = t >> 4;        // -> m = bm + ty + 16*i
    const int bm = blockIdx.y * 64;
    const int bn = blockIdx.x * 64;

    const int lk = t & 15;        // k within tile (coalesced global reads)
    const int lm = t >> 4;        // row group 0..15

    float acc[4][4] = {};

    for (int k0 = 0; k0 < K; k0 += 16) {
        #pragma unroll
        for (int i = 0; i < 4; i++) {
            As[lk][lm + 16 * i] = A [(size_t)(bm + lm + 16 * i) * lda + k0 + lk];
            Bs[lk][lm + 16 * i] = Bm[(size_t)(bn + lm + 16 * i) * ldb + k0 + lk];
        }
        __syncthreads();
        #pragma unroll
        for (int k = 0; k < 16; k++) {
            float a[4], b[4];
            #pragma unroll
            for (int i = 0; i < 4; i++) { a[i] = As[k][ty + 16 * i]; b[i] = Bs[k][tx + 16 * i]; }
            #pragma unroll
            for (int i = 0; i < 4; i++)
                #pragma unroll
                for (int j = 0; j < 4; j++)
                    acc[i][j] += a[i] * b[j];
        }
        __syncthreads();
    }

    #pragma unroll
    for (int i = 0; i < 4; i++) {
        int m = bm + ty + 16 * i;
        #pragma unroll
        for (int j = 0; j < 4; j++) {
            int n = bn + tx + 16 * j;
            float r = acc[i][j] * alpha;
            if (bias) r += bias[n];
            C[(size_t)m * ldc + n] = r;
        }
    }
}

// ---------------------------------------------------------------------------
// Generic batched SGEMM, NN form:  C[m,n] = alpha * sum_k A[m,k] * B[k,n] + bias[n]
// B row-major [K,N] (ldb).
// ---------------------------------------------------------------------------
__global__ __launch_bounds__(256)
void gemm_nn(const float* __restrict__ A, int lda, long aOut, long aIn,
             const float* __restrict__ Bm, int ldb, long bOut, long bIn,
             const float* __restrict__ bias,
             float* __restrict__ C, int ldc, long cOut, long cIn,
             int K, float alpha)
{
    int z = blockIdx.z;
    int bo = z >> 3, bi = z & 7;
    A  += (size_t)bo * aOut + (size_t)bi * aIn;
    Bm += (size_t)bo * bOut + (size_t)bi * bIn;
    C  += (size_t)bo * cOut + (size_t)bi * cIn;

    __shared__ float As[16][65];
    __shared__ float Bs[16][65];

    const int t  = threadIdx.x;
    const int tx = t & 15;
    const int ty = t >> 4;
    const int bm = blockIdx.y * 64;
    const int bn = blockIdx.x * 64;

    const int lk  = t & 15;       // A-load: k
    const int lm  = t >> 4;       // A-load: row group
    const int ln  = t & 63;       // B-load: n (coalesced)
    const int lkB = t >> 6;       // B-load: k group 0..3

    float acc[4][4] = {};

    for (int k0 = 0; k0 < K; k0 += 16) {
        #pragma unroll
        for (int i = 0; i < 4; i++)
            As[lk][lm + 16 * i] = A[(size_t)(bm + lm + 16 * i) * lda + k0 + lk];
        #pragma unroll
        for (int i = 0; i < 4; i++)
            Bs[lkB + 4 * i][ln] = Bm[(size_t)(k0 + lkB + 4 * i) * ldb + bn + ln];
        __syncthreads();
        #pragma unroll
        for (int k = 0; k < 16; k++) {
            float a[4], b[4];
            #pragma unroll
            for (int i = 0; i < 4; i++) { a[i] = As[k][ty + 16 * i]; b[i] = Bs[k][tx + 16 * i]; }
            #pragma unroll
            for (int i = 0; i < 4; i++)
                #pragma unroll
                for (int j = 0; j < 4; j++)
                    acc[i][j] += a[i] * b[j];
        }
        __syncthreads();
    }

    #pragma unroll
    for (int i = 0; i < 4; i++) {
        int m = bm + ty + 16 * i;
        #pragma unroll
        for (int j = 0; j < 4; j++) {
            int n = bn + tx + 16 * j;
            float r = acc[i][j] * alpha;
            if (bias) r += bias[n];
            C[(size_t)m * ldc + n] = r;
        }
    }
}

// ---------------------------------------------------------------------------
// Row softmax over 2048-wide rows. One block (256 threads) per row.
// ---------------------------------------------------------------------------
__global__ __launch_bounds__(256)
void softmax_rows(float* __restrict__ S)
{
    float* row = S + (size_t)blockIdx.x * SEQ;
    const int t = threadIdx.x;
    __shared__ float red[256];

    float v[8];
    float mx = -1e30f;
    #pragma unroll
    for (int i = 0; i < 8; i++) {
        v[i] = row[t + i * 256];
        mx = fmaxf(mx, v[i]);
    }
    red[t] = mx;
    __syncthreads();
    for (int s = 128; s > 0; s >>= 1) {
        if (t < s) red[t] = fmaxf(red[t], red[t + s]);
        __syncthreads();
    }
    mx = red[0];
    __syncthreads();

    float sum = 0.f;
    #pragma unroll
    for (int i = 0; i < 8; i++) {
        v[i] = __expf(v[i] - mx);
        sum += v[i];
    }
    red[t] = sum;
    __syncthreads();
    for (int s = 128; s > 0; s >>= 1) {
        if (t < s) red[t] += red[t + s];
        __syncthreads();
    }
    float inv = 1.0f / red[0];
    #pragma unroll
    for (int i = 0; i < 8; i++)
        row[t + i * 256] = v[i] * inv;
}

// ---------------------------------------------------------------------------
extern "C" void kernel_launch(void* const* d_in, const int* in_sizes, int n_in,
                              void* d_out, int out_size)
{
    const float* x    = (const float*)d_in[0];   // [4, 2048, 1024]
    const float* Wqkv = (const float*)d_in[1];   // [3072, 1024]
    const float* bqkv = (const float*)d_in[2];   // [3072]
    const float* W0   = (const float*)d_in[3];   // [1024, 1024]
    const float* b0   = (const float*)d_in[4];   // [1024]
    float* out = (float*)d_out;                  // [4, 2048, 1024]

    float *qkv, *scores, *ctx;
    cudaGetSymbolAddress((void**)&qkv,    g_qkv);
    cudaGetSymbolAddress((void**)&scores, g_scores);
    cudaGetSymbolAddress((void**)&ctx,    g_ctx);

    const float SCALE = 11.313708498984761f;  // sqrt(128)

    const int M  = BATCH * SEQ;      // 8192
    dim3 blk(256);

    // 1) QKV projection: qkv[M, 3072] = x[M,1024] @ Wqkv^T + bqkv
    {
        dim3 grid(QKV_DIM / 64, M / 64, 1);
        gemm_nt<<<grid, blk>>>(x, DIM, 0, 0,
                               Wqkv, DIM, 0, 0,
                               bqkv,
                               qkv, QKV_DIM, 0, 0,
                               DIM, 1.0f);
    }

    // 2) Scores: S[z] = Q[z] @ K[z]^T * SCALE   (z = b*8 + h, 32 batches)
    {
        dim3 grid(SEQ / 64, SEQ / 64, BATCH * HEADS);
        gemm_nt<<<grid, blk>>>(qkv /*Q base, s=0*/, QKV_DIM,
                               (long)SEQ * QKV_DIM, HDIM,
                               qkv + DIM /*K base, s=1*/, QKV_DIM,
                               (long)SEQ * QKV_DIM, HDIM,
                               nullptr,
                               scores, SEQ,
                               (long)HEADS * SEQ * SEQ, (long)SEQ * SEQ,
                               HDIM, SCALE);
    }

    // 3) Softmax over rows of S
    {
        dim3 grid(BATCH * HEADS * SEQ);
        softmax_rows<<<grid, blk>>>(scores);
    }

    // 4) Context: ctx[b,n,h*128+d] = sum_m S[z,n,m] * V[z,m,d]
    {
        dim3 grid(HDIM / 64, SEQ / 64, BATCH * HEADS);
        gemm_nn<<<grid, blk>>>(scores, SEQ,
                               (long)HEADS * SEQ * SEQ, (long)SEQ * SEQ,
                               qkv + 2 * DIM /*V base, s=2*/, QKV_DIM,
                               (long)SEQ * QKV_DIM, HDIM,
                               nullptr,
                               ctx, DIM,
                               (long)SEQ * DIM, HDIM,
                               SEQ, 1.0f);
    }

    // 5) Output projection: out[M,1024] = ctx[M,1024] @ W0^T + b0
    {
        dim3 grid(DIM / 64, M / 64, 1);
        gemm_nt<<<grid, blk>>>(ctx, DIM, 0, 0,
                               W0, DIM, 0, 0,
                               b0,
                               out, DIM, 0, 0,
                               DIM, 1.0f);
    }
}

// round 5
// speedup vs baseline: 1.7688x; 1.7688x over previous
#include <cuda_runtime.h>
#include <cuda_bf16.h>
#include <math.h>

// Problem constants
#define BATCH   4
#define SEQ     2048
#define DIM     1024
#define HEADS   8
#define HDIM    128            // DIM / HEADS
#define QKV_DIM (3 * DIM)      // 3072

// Scratch (module globals — allowed; no runtime allocation)
__device__ float g_qkv[(size_t)BATCH * SEQ * QKV_DIM];            // 100.7 MB
__device__ float g_scores[(size_t)BATCH * HEADS * SEQ * SEQ];     // 536.9 MB
__device__ float g_ctx[(size_t)BATCH * SEQ * DIM];                // 33.6 MB

#define TM 128
#define TN 128
#define TK 8

// ---------------------------------------------------------------------------
// 128x128x8 tile, 256 threads, 8x8 micro-tile, float4 LDS fragments.
// tx = t & 15 (n), ty = t >> 4 (m).
// m indices: ty*4 + {0..3}, ty*4 + 64 + {0..3}
// n indices: tx*4 + {0..3}, tx*4 + 64 + {0..3}
// ---------------------------------------------------------------------------

// NT form:  C[m,n] = alpha * sum_k A[m,k] * B[n,k] + bias[n]
__global__ __launch_bounds__(256)
void gemm_nt(const float* __restrict__ A, int lda, long aOut, long aIn,
             const float* __restrict__ Bm, int ldb, long bOut, long bIn,
             const float* __restrict__ bias,
             float* __restrict__ C, int ldc, long cOut, long cIn,
             int K, float alpha)
{
    int z = blockIdx.z;
    int bo = z >> 3, bi = z & 7;
    A  += (size_t)bo * aOut + (size_t)bi * aIn;
    Bm += (size_t)bo * bOut + (size_t)bi * bIn;
    C  += (size_t)bo * cOut + (size_t)bi * cIn;

    __shared__ float As[TK][TM];
    __shared__ float Bs[TK][TN];

    const int t  = threadIdx.x;
    const int tx = t & 15;
    const int ty = t >> 4;
    const int bm = blockIdx.y * TM;
    const int bn = blockIdx.x * TN;

    const int lr = t >> 1;          // row 0..127
    const int lk = (t & 1) * 4;     // k sub-offset 0 or 4

    const float* Aptr = A  + (size_t)(bm + lr) * lda + lk;
    const float* Bptr = Bm + (size_t)(bn + lr) * ldb + lk;

    float4 ra = *(const float4*)Aptr;
    float4 rb = *(const float4*)Bptr;

    float acc[8][8] = {};

    for (int k0 = 0; k0 < K; k0 += TK) {
        As[lk + 0][lr] = ra.x; As[lk + 1][lr] = ra.y;
        As[lk + 2][lr] = ra.z; As[lk + 3][lr] = ra.w;
        Bs[lk + 0][lr] = rb.x; Bs[lk + 1][lr] = rb.y;
        Bs[lk + 2][lr] = rb.z; Bs[lk + 3][lr] = rb.w;
        __syncthreads();

        if (k0 + TK < K) {               // prefetch next tile (overlaps compute)
            ra = *(const float4*)(Aptr + k0 + TK);
            rb = *(const float4*)(Bptr + k0 + TK);
        }

        #pragma unroll
        for (int k = 0; k < TK; k++) {
            float a[8], b[8];
            *(float4*)&a[0] = *(const float4*)&As[k][ty * 4];
            *(float4*)&a[4] = *(const float4*)&As[k][ty * 4 + 64];
            *(float4*)&b[0] = *(const float4*)&Bs[k][tx * 4];
            *(float4*)&b[4] = *(const float4*)&Bs[k][tx * 4 + 64];
            #pragma unroll
            for (int i = 0; i < 8; i++)
                #pragma unroll
                for (int j = 0; j < 8; j++)
                    acc[i][j] += a[i] * b[j];
        }
        __syncthreads();
    }

    #pragma unroll
    for (int i = 0; i < 8; i++) {
        int m = bm + ty * 4 + ((i < 4) ? i : (60 + i));
        #pragma unroll
        for (int jh = 0; jh < 2; jh++) {
            int n = bn + tx * 4 + jh * 64;
            float4 r;
            r.x = acc[i][jh * 4 + 0] * alpha;
            r.y = acc[i][jh * 4 + 1] * alpha;
            r.z = acc[i][jh * 4 + 2] * alpha;
            r.w = acc[i][jh * 4 + 3] * alpha;
            if (bias) {
                r.x += bias[n + 0]; r.y += bias[n + 1];
                r.z += bias[n + 2]; r.w += bias[n + 3];
            }
            *(float4*)&C[(size_t)m * ldc + n] = r;
        }
    }
}

// NN form:  C[m,n] = alpha * sum_k A[m,k] * B[k,n] + bias[n]
__global__ __launch_bounds__(256)
void gemm_nn(const float* __restrict__ A, int lda, long aOut, long aIn,
             const float* __restrict__ Bm, int ldb, long bOut, long bIn,
             const float* __restrict__ bias,
             float* __restrict__ C, int ldc, long cOut, long cIn,
             int K, float alpha)
{
    int z = blockIdx.z;
    int bo = z >> 3, bi = z & 7;
    A  += (size_t)bo * aOut + (size_t)bi * aIn;
    Bm += (size_t)bo * bOut + (size_t)bi * bIn;
    C  += (size_t)bo * cOut + (size_t)bi * cIn;

    __shared__ float As[TK][TM];
    __shared__ float Bs[TK][TN];

    const int t  = threadIdx.x;
    const int tx = t & 15;
    const int ty = t >> 4;
    const int bm = blockIdx.y * TM;
    const int bn = blockIdx.x * TN;

    const int lr = t >> 1;          // A row 0..127
    const int lk = (t & 1) * 4;     // A k sub-offset

    const int lkB = t >> 5;         // B k row 0..7
    const int lnB = (t & 31) * 4;   // B n offset (coalesced)

    const float* Aptr = A  + (size_t)(bm + lr) * lda + lk;
    const float* Bptr = Bm + (size_t)lkB * ldb + bn + lnB;

    float4 ra = *(const float4*)Aptr;
    float4 rb = *(const float4*)Bptr;

    float acc[8][8] = {};

    for (int k0 = 0; k0 < K; k0 += TK) {
        As[lk + 0][lr] = ra.x; As[lk + 1][lr] = ra.y;
        As[lk + 2][lr] = ra.z; As[lk + 3][lr] = ra.w;
        *(float4*)&Bs[lkB][lnB] = rb;
        __syncthreads();

        if (k0 + TK < K) {
            ra = *(const float4*)(Aptr + k0 + TK);
            rb = *(const float4*)(Bptr + (size_t)(k0 + TK) * ldb);
        }

        #pragma unroll
        for (int k = 0; k < TK; k++) {
            float a[8], b[8];
            *(float4*)&a[0] = *(const float4*)&As[k][ty * 4];
            *(float4*)&a[4] = *(const float4*)&As[k][ty * 4 + 64];
            *(float4*)&b[0] = *(const float4*)&Bs[k][tx * 4];
            *(float4*)&b[4] = *(const float4*)&Bs[k][tx * 4 + 64];
            #pragma unroll
            for (int i = 0; i < 8; i++)
                #pragma unroll
                for (int j = 0; j < 8; j++)
                    acc[i][j] += a[i] * b[j];
        }
        __syncthreads();
    }

    #pragma unroll
    for (int i = 0; i < 8; i++) {
        int m = bm + ty * 4 + ((i < 4) ? i : (60 + i));
        #pragma unroll
        for (int jh = 0; jh < 2; jh++) {
            int n = bn + tx * 4 + jh * 64;
            float4 r;
            r.x = acc[i][jh * 4 + 0] * alpha;
            r.y = acc[i][jh * 4 + 1] * alpha;
            r.z = acc[i][jh * 4 + 2] * alpha;
            r.w = acc[i][jh * 4 + 3] * alpha;
            if (bias) {
                r.x += bias[n + 0]; r.y += bias[n + 1];
                r.z += bias[n + 2]; r.w += bias[n + 3];
            }
            *(float4*)&C[(size_t)m * ldc + n] = r;
        }
    }
}

// ---------------------------------------------------------------------------
// Row softmax over 2048-wide rows. One block (256 threads) per row.
// Warp-shuffle reductions; float4 I/O; only 2 block-wide syncs.
// ---------------------------------------------------------------------------
__global__ __launch_bounds__(256)
void softmax_rows(float* __restrict__ S)
{
    float* row = S + (size_t)blockIdx.x * SEQ;
    const int t    = threadIdx.x;
    const int lane = t & 31;
    const int warp = t >> 5;
    __shared__ float red[8];

    // Each thread owns 2 float4s: elements 8t..8t+7 (contiguous 32B, coalesced)
    float4 v0 = *(const float4*)&row[t * 8];
    float4 v1 = *(const float4*)&row[t * 8 + 4];

    float mx = fmaxf(fmaxf(fmaxf(v0.x, v0.y), fmaxf(v0.z, v0.w)),
                     fmaxf(fmaxf(v1.x, v1.y), fmaxf(v1.z, v1.w)));
    #pragma unroll
    for (int s = 16; s > 0; s >>= 1)
        mx = fmaxf(mx, __shfl_xor_sync(0xffffffffu, mx, s));
    if (lane == 0) red[warp] = mx;
    __syncthreads();
    {
        float m = red[lane & 7];
        #pragma unroll
        for (int s = 4; s > 0; s >>= 1)
            m = fmaxf(m, __shfl_xor_sync(0xffffffffu, m, s));
        mx = m;   // every thread now has the block max
    }

    v0.x = __expf(v0.x - mx); v0.y = __expf(v0.y - mx);
    v0.z = __expf(v0.z - mx); v0.w = __expf(v0.w - mx);
    v1.x = __expf(v1.x - mx); v1.y = __expf(v1.y - mx);
    v1.z = __expf(v1.z - mx); v1.w = __expf(v1.w - mx);

    float sum = (v0.x + v0.y) + (v0.z + v0.w) + (v1.x + v1.y) + (v1.z + v1.w);
    #pragma unroll
    for (int s = 16; s > 0; s >>= 1)
        sum += __shfl_xor_sync(0xffffffffu, sum, s);
    __syncthreads();              // protect red[] reuse
    if (lane == 0) red[warp] = sum;
    __syncthreads();
    {
        float s8 = red[lane & 7];
        #pragma unroll
        for (int s = 4; s > 0; s >>= 1)
            s8 += __shfl_xor_sync(0xffffffffu, s8, s);
        sum = s8;
    }

    float inv = 1.0f / sum;
    v0.x *= inv; v0.y *= inv; v0.z *= inv; v0.w *= inv;
    v1.x *= inv; v1.y *= inv; v1.z *= inv; v1.w *= inv;
    *(float4*)&row[t * 8]     = v0;
    *(float4*)&row[t * 8 + 4] = v1;
}

// ---------------------------------------------------------------------------
extern "C" void kernel_launch(void* const* d_in, const int* in_sizes, int n_in,
                              void* d_out, int out_size)
{
    const float* x    = (const float*)d_in[0];   // [4, 2048, 1024]
    const float* Wqkv = (const float*)d_in[1];   // [3072, 1024]
    const float* bqkv = (const float*)d_in[2];   // [3072]
    const float* W0   = (const float*)d_in[3];   // [1024, 1024]
    const float* b0   = (const float*)d_in[4];   // [1024]
    float* out = (float*)d_out;                  // [4, 2048, 1024]

    float *qkv, *scores, *ctx;
    cudaGetSymbolAddress((void**)&qkv,    g_qkv);
    cudaGetSymbolAddress((void**)&scores, g_scores);
    cudaGetSymbolAddress((void**)&ctx,    g_ctx);

    const float SCALE = 11.313708498984761f;  // sqrt(128)

    const int M  = BATCH * SEQ;      // 8192
    dim3 blk(256);

    // 1) QKV projection: qkv[M, 3072] = x[M,1024] @ Wqkv^T + bqkv
    {
        dim3 grid(QKV_DIM / TN, M / TM, 1);
        gemm_nt<<<grid, blk>>>(x, DIM, 0, 0,
                               Wqkv, DIM, 0, 0,
                               bqkv,
                               qkv, QKV_DIM, 0, 0,
                               DIM, 1.0f);
    }

    // 2) Scores: S[z] = Q[z] @ K[z]^T * SCALE   (z = b*8 + h, 32 batches)
    {
        dim3 grid(SEQ / TN, SEQ / TM, BATCH * HEADS);
        gemm_nt<<<grid, blk>>>(qkv /*Q base, s=0*/, QKV_DIM,
                               (long)SEQ * QKV_DIM, HDIM,
                               qkv + DIM /*K base, s=1*/, QKV_DIM,
                               (long)SEQ * QKV_DIM, HDIM,
                               nullptr,
                               scores, SEQ,
                               (long)HEADS * SEQ * SEQ, (long)SEQ * SEQ,
                               HDIM, SCALE);
    }

    // 3) Softmax over rows of S
    {
        dim3 grid(BATCH * HEADS * SEQ);
        softmax_rows<<<grid, blk>>>(scores);
    }

    // 4) Context: ctx[b,n,h*128+d] = sum_m S[z,n,m] * V[z,m,d]
    {
        dim3 grid(HDIM / TN, SEQ / TM, BATCH * HEADS);   // (1, 16, 32)
        gemm_nn<<<grid, blk>>>(scores, SEQ,
                               (long)HEADS * SEQ * SEQ, (long)SEQ * SEQ,
                               qkv + 2 * DIM /*V base, s=2*/, QKV_DIM,
                               (long)SEQ * QKV_DIM, HDIM,
                               nullptr,
                               ctx, DIM,
                               (long)SEQ * DIM, HDIM,
                               SEQ, 1.0f);
    }

    // 5) Output projection: out[M,1024] = ctx[M,1024] @ W0^T + b0
    {
        dim3 grid(DIM / TN, M / TM, 1);
        gemm_nt<<<grid, blk>>>(ctx, DIM, 0, 0,
                               W0, DIM, 0, 0,
                               b0,
                               out, DIM, 0, 0,
                               DIM, 1.0f);
    }
}